// round 4
// baseline (speedup 1.0000x reference)
#include <cuda_runtime.h>
#include <cstdint>
#include <cstddef>

// Problem: out[n,b,o] = (x @ (W*(noise[n]-1)))[b,o] * rsqrt((x^2 @ W^2)[b,o])
// x: [128,784] f32, W: [784,1024] f32, noise: [500,784,1024] f32
// out: [500*128, 1024] f32
#define BB 128
#define KK 784
#define OO 1024
#define NN 500

// ---------------- main GEMM tiling ----------------
#define XS_STRIDE 36              // 32 + 4 pad -> conflict-free A frag LDS
#define BS_STRIDE 136             // 128 + 8 pad -> conflict-free B frag LDS
#define XS_SIZE (128 * XS_STRIDE) // 4608 u32
#define BS_SIZE (32 * BS_STRIDE)  // 4352 u32
#define SMEM_U32 (2 * XS_SIZE + 4 * BS_SIZE) // double buffer, 2 n's
#define SMEM_BYTES (SMEM_U32 * 4)            // 106496 B

// ---------------- device scratch (no allocations allowed) ----------------
__device__ float g_part[8 * 128 * 1024]; // k-split partials of x^2 @ W^2
__device__ float g_S[128 * 1024];        // rsqrt(x^2 @ W^2)

// ---------------- helpers ----------------
__device__ __forceinline__ uint32_t f2tf(float f) {
    uint32_t r;
    asm("cvt.rna.tf32.f32 %0, %1;" : "=r"(r) : "f"(f));
    return r;
}

__device__ __forceinline__ void mma8(float* d, const uint32_t* a, uint32_t b0, uint32_t b1) {
    asm volatile(
        "mma.sync.aligned.m16n8k8.row.col.f32.tf32.tf32.f32 "
        "{%0,%1,%2,%3},{%4,%5,%6,%7},{%8,%9},{%0,%1,%2,%3};"
        : "+f"(d[0]), "+f"(d[1]), "+f"(d[2]), "+f"(d[3])
        : "r"(a[0]), "r"(a[1]), "r"(a[2]), "r"(a[3]), "r"(b0), "r"(b1));
}

// ================= S = rsqrt(x^2 @ W^2), exact fp32 =================
// grid (4 o-tiles of 256, 8 b-tiles of 16, 8 k-slices of 98), block 256.
__global__ void s_partial_kernel(const float* __restrict__ x, const float* __restrict__ W) {
    __shared__ float xsq[16][17];
    const int o = blockIdx.x * 256 + threadIdx.x;
    const int b0 = blockIdx.y * 16;
    const int ks = blockIdx.z;
    const int k0 = ks * 98;

    float acc[16];
#pragma unroll
    for (int i = 0; i < 16; i++) acc[i] = 0.f;

    const int bi = threadIdx.x >> 4;
    const int jj = threadIdx.x & 15;

    for (int kk = 0; kk < 98; kk += 16) {
        int jmax = 98 - kk;
        if (jmax > 16) jmax = 16;
        if (jj < jmax) {
            float v = x[(b0 + bi) * KK + k0 + kk + jj];
            xsq[bi][jj] = v * v;
        }
        __syncthreads();
        for (int j = 0; j < jmax; j++) {
            float w = __ldg(W + (size_t)(k0 + kk + j) * OO + o);
            w *= w;
#pragma unroll
            for (int b = 0; b < 16; b++) acc[b] = fmaf(xsq[b][j], w, acc[b]);
        }
        __syncthreads();
    }
#pragma unroll
    for (int b = 0; b < 16; b++)
        g_part[((size_t)ks * 128 + b0 + b) * OO + o] = acc[b];
}

__global__ void s_reduce_kernel() {
    int i = blockIdx.x * 256 + threadIdx.x; // 131072 total
    float s = 0.f;
#pragma unroll
    for (int ks = 0; ks < 8; ks++) s += g_part[(size_t)ks * 131072 + i];
    g_S[i] = 1.0f / sqrtf(s);
}

// ================= main: 500 tf32 GEMMs =================
// Grid: (8 o-tiles of 128, 250 n-pairs). Block: 256 threads = 8 warps (2x4),
// warp tile 64x32, 2 iterations (NG=2) accumulated simultaneously.

__device__ __forceinline__ void ldg_stage(
    const float* __restrict__ x, const float* __restrict__ W,
    const float* __restrict__ noise,
    int kb, int n0, int o0, int tid,
    float4* xv, float4* wv, float4* nv0, float4* nv1)
{
    const int lane = tid & 31, wid = tid >> 5;
    const float4 z = make_float4(0.f, 0.f, 0.f, 0.f);
#pragma unroll
    for (int r = 0; r < 4; r++) {
        int b = r * 32 + (tid >> 3);
        int k = kb + (tid & 7) * 4;
        xv[r] = (k < KK) ? __ldg(reinterpret_cast<const float4*>(x + b * KK + k)) : z;
    }
#pragma unroll
    for (int r = 0; r < 4; r++) {
        int gk = kb + r * 8 + wid;
        if (gk < KK) {
            size_t idx = (size_t)gk * OO + o0 + lane * 4;
            wv[r]  = __ldg(reinterpret_cast<const float4*>(W + idx));
            nv0[r] = __ldg(reinterpret_cast<const float4*>(noise + (size_t)n0 * KK * OO + idx));
            nv1[r] = __ldg(reinterpret_cast<const float4*>(noise + (size_t)(n0 + 1) * KK * OO + idx));
        } else {
            wv[r] = z; nv0[r] = z; nv1[r] = z;
        }
    }
}

__device__ __forceinline__ void sts_stage(
    uint32_t* __restrict__ xs, uint32_t* __restrict__ bs0, uint32_t* __restrict__ bs1,
    int tid, const float4* xv, const float4* wv, const float4* nv0, const float4* nv1)
{
    const int lane = tid & 31, wid = tid >> 5;
#pragma unroll
    for (int r = 0; r < 4; r++) {
        int b = r * 32 + (tid >> 3);
        int kq = tid & 7;
        uint4 v;
        v.x = f2tf(xv[r].x); v.y = f2tf(xv[r].y);
        v.z = f2tf(xv[r].z); v.w = f2tf(xv[r].w);
        *reinterpret_cast<uint4*>(xs + b * XS_STRIDE + kq * 4) = v;
    }
#pragma unroll
    for (int r = 0; r < 4; r++) {
        int k = r * 8 + wid;
        uint4 v0, v1;
        v0.x = f2tf((nv0[r].x - 1.f) * wv[r].x);
        v0.y = f2tf((nv0[r].y - 1.f) * wv[r].y);
        v0.z = f2tf((nv0[r].z - 1.f) * wv[r].z);
        v0.w = f2tf((nv0[r].w - 1.f) * wv[r].w);
        v1.x = f2tf((nv1[r].x - 1.f) * wv[r].x);
        v1.y = f2tf((nv1[r].y - 1.f) * wv[r].y);
        v1.z = f2tf((nv1[r].z - 1.f) * wv[r].z);
        v1.w = f2tf((nv1[r].w - 1.f) * wv[r].w);
        *reinterpret_cast<uint4*>(bs0 + k * BS_STRIDE + lane * 4) = v0;
        *reinterpret_cast<uint4*>(bs1 + k * BS_STRIDE + lane * 4) = v1;
    }
}

__device__ __forceinline__ void compute_kstep(
    const uint32_t* __restrict__ xs,
    const uint32_t* __restrict__ bs0, const uint32_t* __restrict__ bs1,
    int ks, int wm, int wn, int g, int t,
    float acc[2][4][4][4])
{
    uint32_t a[4][4];
#pragma unroll
    for (int mt = 0; mt < 4; mt++) {
        const uint32_t* p = xs + (wm * 64 + mt * 16 + g) * XS_STRIDE + ks * 8 + t;
        a[mt][0] = p[0];
        a[mt][1] = p[8 * XS_STRIDE];
        a[mt][2] = p[4];
        a[mt][3] = p[8 * XS_STRIDE + 4];
    }
#pragma unroll
    for (int ng = 0; ng < 2; ng++) {
        const uint32_t* bs = ng ? bs1 : bs0;
#pragma unroll
        for (int nt = 0; nt < 4; nt++) {
            const int ncol = wn * 32 + nt * 8 + g;
            uint32_t b0 = bs[(ks * 8 + t) * BS_STRIDE + ncol];
            uint32_t b1 = bs[(ks * 8 + t + 4) * BS_STRIDE + ncol];
#pragma unroll
            for (int mt = 0; mt < 4; mt++)
                mma8(acc[ng][mt][nt], a[mt], b0, b1);
        }
    }
}

__global__ void __launch_bounds__(256, 1) wn_main_kernel(
    const float* __restrict__ x, const float* __restrict__ W,
    const float* __restrict__ noise, float* __restrict__ out)
{
    extern __shared__ uint32_t sm[];
    const int tid = threadIdx.x;
    const int o0 = blockIdx.x * 128;
    const int n0 = blockIdx.y * 2;
    const int lane = tid & 31, wid = tid >> 5;
    const int g = lane >> 2, t = lane & 3;
    const int wm = wid >> 2, wn = wid & 3;

    uint32_t* xsb[2];
    xsb[0] = sm;
    xsb[1] = sm + XS_SIZE;
    uint32_t* bbase = sm + 2 * XS_SIZE;
    uint32_t* bsb[2][2];
    bsb[0][0] = bbase;
    bsb[0][1] = bbase + BS_SIZE;
    bsb[1][0] = bbase + 2 * BS_SIZE;
    bsb[1][1] = bbase + 3 * BS_SIZE;

    float acc[2][4][4][4];
#pragma unroll
    for (int i = 0; i < 2; i++)
#pragma unroll
        for (int j = 0; j < 4; j++)
#pragma unroll
            for (int k2 = 0; k2 < 4; k2++)
#pragma unroll
                for (int l = 0; l < 4; l++) acc[i][j][k2][l] = 0.f;

    // prologue: stage chunk 0 into buffer 0
    {
        float4 xv[4], wv[4], nv0[4], nv1[4];
        ldg_stage(x, W, noise, 0, n0, o0, tid, xv, wv, nv0, nv1);
        sts_stage(xsb[0], bsb[0][0], bsb[0][1], tid, xv, wv, nv0, nv1);
    }
    __syncthreads();

    for (int kc = 0; kc < 25; kc++) {
        const int cur = kc & 1;
        const int nxt = cur ^ 1;
        const bool pre = (kc + 1) < 25;
        float4 xv[4], wv[4], nv0[4], nv1[4];
        if (pre) ldg_stage(x, W, noise, (kc + 1) * 32, n0, o0, tid, xv, wv, nv0, nv1);
        compute_kstep(xsb[cur], bsb[cur][0], bsb[cur][1], 0, wm, wn, g, t, acc);
        compute_kstep(xsb[cur], bsb[cur][0], bsb[cur][1], 1, wm, wn, g, t, acc);
        if (pre) sts_stage(xsb[nxt], bsb[nxt][0], bsb[nxt][1], tid, xv, wv, nv0, nv1);
        compute_kstep(xsb[cur], bsb[cur][0], bsb[cur][1], 2, wm, wn, g, t, acc);
        compute_kstep(xsb[cur], bsb[cur][0], bsb[cur][1], 3, wm, wn, g, t, acc);
        __syncthreads();
    }

    // epilogue: scale by S, store
#pragma unroll
    for (int mt = 0; mt < 4; mt++) {
        const int row = wm * 64 + mt * 16 + g;
#pragma unroll
        for (int nt = 0; nt < 4; nt++) {
            const int col = o0 + wn * 32 + nt * 8 + 2 * t;
            const float2 s0 = *reinterpret_cast<const float2*>(g_S + row * OO + col);
            const float2 s1 = *reinterpret_cast<const float2*>(g_S + (row + 8) * OO + col);
#pragma unroll
            for (int ng = 0; ng < 2; ng++) {
                const float* a4 = acc[ng][mt][nt];
                float2 v0 = make_float2(a4[0] * s0.x, a4[1] * s0.y);
                float2 v1 = make_float2(a4[2] * s1.x, a4[3] * s1.y);
                size_t base = ((size_t)(n0 + ng) * 128 + row) * OO + col;
                *reinterpret_cast<float2*>(out + base) = v0;
                *reinterpret_cast<float2*>(out + base + 8 * OO) = v1;
            }
        }
    }
}

// ================= launch =================
extern "C" void kernel_launch(void* const* d_in, const int* in_sizes, int n_in,
                              void* d_out, int out_size) {
    const float* x = nullptr;
    const float* W = nullptr;
    const float* noise = nullptr;
    for (int i = 0; i < n_in; i++) {
        if (in_sizes[i] == BB * KK) x = (const float*)d_in[i];
        else if (in_sizes[i] == KK * OO) W = (const float*)d_in[i];
        else if (in_sizes[i] == NN * KK * OO) noise = (const float*)d_in[i];
    }
    float* out = (float*)d_out;

    cudaFuncSetAttribute(wn_main_kernel, cudaFuncAttributeMaxDynamicSharedMemorySize, SMEM_BYTES);

    s_partial_kernel<<<dim3(4, 8, 8), 256>>>(x, W);
    s_reduce_kernel<<<512, 256>>>();
    wn_main_kernel<<<dim3(8, 250), 256, SMEM_BYTES>>>(x, W, noise, out);
}